// round 5
// baseline (speedup 1.0000x reference)
#include <cuda_runtime.h>
#include <math.h>

// MaskedLightAdaIN fused: x [16,64,256,256] f32, mask [16,1,256,256] f32
// out = where(mask>=0.5, x, x*scale + bias) with per-(B,C) masked stats.
//
// One block per HALF plane (128 KB of x cached in SMEM). The two blocks of a
// plane combine partial sums through global atomics; the last one to arrive
// finalizes the stats and publishes them; the other spins on a flag. Apply
// phase then reads x from SMEM — x is read from DRAM exactly once.

#define NB      16
#define NC      64
#define NBC     1024            // planes
#define HW      65536
#define HW4     16384           // float4 per plane
#define HALF4   8192            // float4 per half plane
#define THREADS 1024
#define EPSV    1e-8f

__device__ float    g_part[NBC][5];   // s_all, q_all, s_fg, q_fg, n_fg
__device__ unsigned g_cnt[NBC];       // 0 -> 1 -> 2(adds done) -> 3(stats ready)
__device__ float2   g_sb[NBC];        // scale, bias

__global__ void init_kernel()
{
    int t = threadIdx.x;
    if (t < NBC) {
        g_cnt[t] = 0u;
        #pragma unroll
        for (int j = 0; j < 5; j++) g_part[t][j] = 0.f;
    }
}

__global__ void __launch_bounds__(THREADS) fused_kernel(const float* __restrict__ x,
                                                        const float* __restrict__ mask,
                                                        float* __restrict__ out)
{
    extern __shared__ unsigned char smem[];
    float4*        sx   = reinterpret_cast<float4*>(smem);                 // 131072 B
    unsigned char* smk  = smem + HALF4 * 16;                               // 8192 B
    float*         red  = reinterpret_cast<float*>(smem + HALF4*16 + HALF4); // 32*5 floats
    float*         bro  = red + 32 * 5;                                    // scale, bias

    const int blk  = blockIdx.x;
    const int p    = blk >> 1;          // plane 0..1023
    const int half = blk & 1;
    const int b    = p >> 6;            // batch

    const float4* __restrict__ xp = reinterpret_cast<const float4*>(x)    + (size_t)p * HW4 + half * HALF4;
    const float4* __restrict__ mp = reinterpret_cast<const float4*>(mask) + (size_t)b * HW4 + half * HALF4;
    float4*       __restrict__ op = reinterpret_cast<float4*>(out)        + (size_t)p * HW4 + half * HALF4;

    // ---- Phase 1: load half-plane into SMEM, accumulate partial sums ----
    float s_all = 0.f, q_all = 0.f, s_fg = 0.f, q_fg = 0.f, n_fg = 0.f;

    #pragma unroll
    for (int k = 0; k < 8; k++) {
        const int i = threadIdx.x + k * THREADS;
        float4 xv = xp[i];
        float4 mv = mp[i];
        sx[i] = xv;

        unsigned m0 = (mv.x >= 0.5f), m1 = (mv.y >= 0.5f),
                 m2 = (mv.z >= 0.5f), m3 = (mv.w >= 0.5f);
        smk[i] = (unsigned char)(m0 | (m1 << 1) | (m2 << 2) | (m3 << 3));

        float w0 = (float)m0, w1 = (float)m1, w2 = (float)m2, w3 = (float)m3;
        float x0 = xv.x, x1 = xv.y, x2 = xv.z, x3 = xv.w;

        s_all += x0 + x1 + x2 + x3;
        q_all += x0*x0 + x1*x1 + x2*x2 + x3*x3;
        s_fg  += x0*w0 + x1*w1 + x2*w2 + x3*w3;
        q_fg  += x0*x0*w0 + x1*x1*w1 + x2*x2*w2 + x3*x3*w3;
        n_fg  += w0 + w1 + w2 + w3;
    }

    // ---- block reduction (32 warps, 5 values) ----
    #pragma unroll
    for (int o = 16; o > 0; o >>= 1) {
        s_all += __shfl_xor_sync(0xffffffffu, s_all, o);
        q_all += __shfl_xor_sync(0xffffffffu, q_all, o);
        s_fg  += __shfl_xor_sync(0xffffffffu, s_fg,  o);
        q_fg  += __shfl_xor_sync(0xffffffffu, q_fg,  o);
        n_fg  += __shfl_xor_sync(0xffffffffu, n_fg,  o);
    }
    const int warp = threadIdx.x >> 5;
    const int lane = threadIdx.x & 31;
    if (lane == 0) {
        red[warp*5 + 0] = s_all;
        red[warp*5 + 1] = q_all;
        red[warp*5 + 2] = s_fg;
        red[warp*5 + 3] = q_fg;
        red[warp*5 + 4] = n_fg;
    }
    __syncthreads();

    if (threadIdx.x < 32) {
        float v0 = red[lane*5 + 0];
        float v1 = red[lane*5 + 1];
        float v2 = red[lane*5 + 2];
        float v3 = red[lane*5 + 3];
        float v4 = red[lane*5 + 4];
        #pragma unroll
        for (int o = 16; o > 0; o >>= 1) {
            v0 += __shfl_xor_sync(0xffffffffu, v0, o);
            v1 += __shfl_xor_sync(0xffffffffu, v1, o);
            v2 += __shfl_xor_sync(0xffffffffu, v2, o);
            v3 += __shfl_xor_sync(0xffffffffu, v3, o);
            v4 += __shfl_xor_sync(0xffffffffu, v4, o);
        }

        if (lane == 0) {
            // publish this block's partials
            atomicAdd(&g_part[p][0], v0);
            atomicAdd(&g_part[p][1], v1);
            atomicAdd(&g_part[p][2], v2);
            atomicAdd(&g_part[p][3], v3);
            atomicAdd(&g_part[p][4], v4);
            __threadfence();
            unsigned old = atomicAdd(&g_cnt[p], 1u);

            float scale, bias;
            if (old == 1u) {
                // I'm the last arriver: finalize stats for the plane
                __threadfence();
                float t0 = g_part[p][0];
                float t1 = g_part[p][1];
                float t2 = g_part[p][2];
                float t3 = g_part[p][3];
                float nf = g_part[p][4];
                float nb = (float)HW - nf;

                float s_b = t0 - t2, q_b = t1 - t3;

                float mu_f  = t2 / nf;
                float var_f = fmaxf(t3 - t2 * mu_f, 0.f) / (nf - 1.f);
                float sig_f = sqrtf(var_f);

                float mu_b  = s_b / nb;
                float var_b = fmaxf(q_b - s_b * mu_b, 0.f) / (nb - 1.f);
                float sig_b = sqrtf(var_b);

                scale = sig_f / (sig_b + EPSV);
                bias  = mu_f - mu_b * scale;

                g_sb[p] = make_float2(scale, bias);
                __threadfence();
                atomicExch(&g_cnt[p], 3u);      // flag: stats ready
            } else {
                // partner hasn't added yet: spin for the ready flag
                unsigned v;
                do {
                    __nanosleep(64);
                    v = atomicAdd(&g_cnt[p], 0u);
                } while (v != 3u);
                __threadfence();
                float2 sb = g_sb[p];
                scale = sb.x;
                bias  = sb.y;
            }
            bro[0] = scale;
            bro[1] = bias;
        }
    }
    __syncthreads();

    const float scale = bro[0];
    const float bias  = bro[1];

    // ---- Phase 2: apply from SMEM, single DRAM write ----
    #pragma unroll
    for (int k = 0; k < 8; k++) {
        const int i = threadIdx.x + k * THREADS;
        float4 xv = sx[i];
        unsigned m = smk[i];

        float4 ov;
        ov.x = (m & 1u) ? xv.x : fmaf(xv.x, scale, bias);
        ov.y = (m & 2u) ? xv.y : fmaf(xv.y, scale, bias);
        ov.z = (m & 4u) ? xv.z : fmaf(xv.z, scale, bias);
        ov.w = (m & 8u) ? xv.w : fmaf(xv.w, scale, bias);

        op[i] = ov;
    }
}

extern "C" void kernel_launch(void* const* d_in, const int* in_sizes, int n_in,
                              void* d_out, int out_size)
{
    const float* x    = (const float*)d_in[0];
    const float* mask = (const float*)d_in[1];
    float* out        = (float*)d_out;

    // 128KB x + 8KB mask bits + reduction/broadcast scratch
    const int smem_bytes = HALF4*16 + HALF4 + (32*5 + 2) * (int)sizeof(float);
    cudaFuncSetAttribute(fused_kernel,
                         cudaFuncAttributeMaxDynamicSharedMemorySize, smem_bytes);

    init_kernel<<<1, THREADS>>>();
    fused_kernel<<<2 * NBC, THREADS, smem_bytes>>>(x, mask, out);
}

// round 6
// speedup vs baseline: 1.2075x; 1.2075x over previous
#include <cuda_runtime.h>
#include <math.h>

// MaskedLightAdaIN fused, quarter-plane tiles for 3-CTA/SM residency.
// x [16,64,256,256] f32, mask [16,1,256,256] f32
// out = where(mask>=0.5, x, x*scale + bias), per-(B,C) masked stats.
//
// 4096 blocks, one per quarter plane (64 KB of x in SMEM). The four blocks
// of a plane publish partial sums to distinct slots; the last to arrive sums
// them in a FIXED order (deterministic), finalizes scale/bias, and raises a
// flag. x is read from DRAM exactly once.

#define NB      16
#define NC      64
#define NBC     1024            // planes
#define HW      65536
#define HW4     16384           // float4 per plane
#define Q4      4096            // float4 per quarter plane
#define THREADS 512
#define EPSV    1e-8f

__device__ float    g_part[NBC][4][5];  // per-quarter: s_all, q_all, s_fg, q_fg, n_fg
__device__ unsigned g_cnt[NBC];         // arrivals; 5 == stats ready
__device__ float2   g_sb[NBC];          // scale, bias

__global__ void init_kernel()
{
    int t = threadIdx.x;
    if (t < NBC) g_cnt[t] = 0u;
}

__global__ void __launch_bounds__(THREADS) fused_kernel(const float* __restrict__ x,
                                                        const float* __restrict__ mask,
                                                        float* __restrict__ out)
{
    extern __shared__ unsigned char smem[];
    float4*        sx  = reinterpret_cast<float4*>(smem);                    // 65536 B
    unsigned char* smk = smem + Q4 * 16;                                     // 4096 B
    float*         red = reinterpret_cast<float*>(smem + Q4*16 + Q4);        // 16*5 floats
    float*         bro = red + 16 * 5;                                       // scale, bias

    const int blk = blockIdx.x;
    const int p   = blk >> 2;           // plane 0..1023
    const int q   = blk & 3;            // quarter
    const int b   = p >> 6;             // batch

    const float4* __restrict__ xp = reinterpret_cast<const float4*>(x)    + (size_t)p * HW4 + q * Q4;
    const float4* __restrict__ mp = reinterpret_cast<const float4*>(mask) + (size_t)b * HW4 + q * Q4;
    float4*       __restrict__ op = reinterpret_cast<float4*>(out)        + (size_t)p * HW4 + q * Q4;

    // ---- Phase 1: stream quarter-plane into SMEM, accumulate partials ----
    float s_all = 0.f, q_all = 0.f, s_fg = 0.f, q_fg = 0.f, n_fg = 0.f;

    #pragma unroll
    for (int k = 0; k < 8; k++) {
        const int i = threadIdx.x + k * THREADS;
        float4 xv = xp[i];
        float4 mv = mp[i];
        sx[i] = xv;

        unsigned m0 = (mv.x >= 0.5f), m1 = (mv.y >= 0.5f),
                 m2 = (mv.z >= 0.5f), m3 = (mv.w >= 0.5f);
        smk[i] = (unsigned char)(m0 | (m1 << 1) | (m2 << 2) | (m3 << 3));

        float w0 = (float)m0, w1 = (float)m1, w2 = (float)m2, w3 = (float)m3;
        float x0 = xv.x, x1 = xv.y, x2 = xv.z, x3 = xv.w;

        s_all += x0 + x1 + x2 + x3;
        q_all += x0*x0 + x1*x1 + x2*x2 + x3*x3;
        s_fg  += x0*w0 + x1*w1 + x2*w2 + x3*w3;
        q_fg  += x0*x0*w0 + x1*x1*w1 + x2*x2*w2 + x3*x3*w3;
        n_fg  += w0 + w1 + w2 + w3;
    }

    // ---- block reduction (16 warps, 5 values) ----
    #pragma unroll
    for (int o = 16; o > 0; o >>= 1) {
        s_all += __shfl_xor_sync(0xffffffffu, s_all, o);
        q_all += __shfl_xor_sync(0xffffffffu, q_all, o);
        s_fg  += __shfl_xor_sync(0xffffffffu, s_fg,  o);
        q_fg  += __shfl_xor_sync(0xffffffffu, q_fg,  o);
        n_fg  += __shfl_xor_sync(0xffffffffu, n_fg,  o);
    }
    const int warp = threadIdx.x >> 5;
    const int lane = threadIdx.x & 31;
    if (lane == 0) {
        red[warp*5 + 0] = s_all;
        red[warp*5 + 1] = q_all;
        red[warp*5 + 2] = s_fg;
        red[warp*5 + 3] = q_fg;
        red[warp*5 + 4] = n_fg;
    }
    __syncthreads();

    if (threadIdx.x < 32) {
        float v0 = (lane < 16) ? red[lane*5 + 0] : 0.f;
        float v1 = (lane < 16) ? red[lane*5 + 1] : 0.f;
        float v2 = (lane < 16) ? red[lane*5 + 2] : 0.f;
        float v3 = (lane < 16) ? red[lane*5 + 3] : 0.f;
        float v4 = (lane < 16) ? red[lane*5 + 4] : 0.f;
        #pragma unroll
        for (int o = 8; o > 0; o >>= 1) {
            v0 += __shfl_xor_sync(0xffffffffu, v0, o);
            v1 += __shfl_xor_sync(0xffffffffu, v1, o);
            v2 += __shfl_xor_sync(0xffffffffu, v2, o);
            v3 += __shfl_xor_sync(0xffffffffu, v3, o);
            v4 += __shfl_xor_sync(0xffffffffu, v4, o);
        }

        if (lane == 0) {
            // publish this quarter's partials to its own slot (no float atomics
            // -> combine order is fixed -> bit-deterministic across replays)
            g_part[p][q][0] = v0;
            g_part[p][q][1] = v1;
            g_part[p][q][2] = v2;
            g_part[p][q][3] = v3;
            g_part[p][q][4] = v4;
            __threadfence();
            unsigned old = atomicAdd(&g_cnt[p], 1u);

            float scale, bias;
            if (old == 3u) {
                // last arriver: all 4 slots visible; sum in fixed order
                __threadfence();
                float t0 = 0.f, t1 = 0.f, t2 = 0.f, t3 = 0.f, nf = 0.f;
                #pragma unroll
                for (int s = 0; s < 4; s++) {
                    t0 += g_part[p][s][0];
                    t1 += g_part[p][s][1];
                    t2 += g_part[p][s][2];
                    t3 += g_part[p][s][3];
                    nf += g_part[p][s][4];
                }
                float nb = (float)HW - nf;
                float s_b = t0 - t2, q_b = t1 - t3;

                float mu_f  = t2 / nf;
                float var_f = fmaxf(t3 - t2 * mu_f, 0.f) / (nf - 1.f);
                float sig_f = sqrtf(var_f);

                float mu_b  = s_b / nb;
                float var_b = fmaxf(q_b - s_b * mu_b, 0.f) / (nb - 1.f);
                float sig_b = sqrtf(var_b);

                scale = sig_f / (sig_b + EPSV);
                bias  = mu_f - mu_b * scale;

                g_sb[p] = make_float2(scale, bias);
                __threadfence();
                atomicExch(&g_cnt[p], 5u);      // stats ready
            } else {
                unsigned v;
                do {
                    __nanosleep(64);
                    v = atomicAdd(&g_cnt[p], 0u);
                } while (v != 5u);
                __threadfence();
                float2 sb = g_sb[p];
                scale = sb.x;
                bias  = sb.y;
            }
            bro[0] = scale;
            bro[1] = bias;
        }
    }
    __syncthreads();

    const float scale = bro[0];
    const float bias  = bro[1];

    // ---- Phase 2: apply from SMEM, single DRAM write ----
    #pragma unroll
    for (int k = 0; k < 8; k++) {
        const int i = threadIdx.x + k * THREADS;
        float4 xv = sx[i];
        unsigned m = smk[i];

        float4 ov;
        ov.x = (m & 1u) ? xv.x : fmaf(xv.x, scale, bias);
        ov.y = (m & 2u) ? xv.y : fmaf(xv.y, scale, bias);
        ov.z = (m & 4u) ? xv.z : fmaf(xv.z, scale, bias);
        ov.w = (m & 8u) ? xv.w : fmaf(xv.w, scale, bias);

        op[i] = ov;
    }
}

extern "C" void kernel_launch(void* const* d_in, const int* in_sizes, int n_in,
                              void* d_out, int out_size)
{
    const float* x    = (const float*)d_in[0];
    const float* mask = (const float*)d_in[1];
    float* out        = (float*)d_out;

    // 64KB x + 4KB mask bits + reduction/broadcast scratch
    const int smem_bytes = Q4*16 + Q4 + (16*5 + 2) * (int)sizeof(float);
    cudaFuncSetAttribute(fused_kernel,
                         cudaFuncAttributeMaxDynamicSharedMemorySize, smem_bytes);

    init_kernel<<<1, 1024>>>();
    fused_kernel<<<4 * NBC, THREADS, smem_bytes>>>(x, mask, out);
}